// round 9
// baseline (speedup 1.0000x reference)
#include <cuda_runtime.h>
#include <cuda_bf16.h>
#include <cstdint>

typedef unsigned long long ull;

#define EPSF 1e-5f

// ---------------- scratch ----------------
__device__ float g_P[(size_t)256 * 208 * 16];   // [c][m][a16], 0.5 folded
__device__ float g_Pb[208 * 16];                // [m][a16], 0.5 folded
__device__ float g_W1T[256 * 128];              // [c][f], BN-scale folded
__device__ float g_bf[128];                     // folded bias
__device__ float g_att[(size_t)13312 * 256];    // attention out, row = a*1024 + b

// ---------------- helpers ----------------
__device__ __forceinline__ ull fma2(ull a, ull b, ull c) {
    ull d;
    asm("fma.rn.f32x2 %0, %1, %2, %3;" : "=l"(d) : "l"(a), "l"(b), "l"(c));
    return d;
}
__device__ __forceinline__ ull dup2(float v) {
    ull d; unsigned r = __float_as_uint(v);
    asm("mov.b64 %0, {%1, %1};" : "=l"(d) : "r"(r));
    return d;
}
__device__ __forceinline__ float lo32(ull a) { return __uint_as_float((unsigned)(a & 0xffffffffull)); }
__device__ __forceinline__ float hi32(ull a) { return __uint_as_float((unsigned)(a >> 32)); }

__device__ __forceinline__ void cpa16(unsigned dst, const void* src) {
    asm volatile("cp.async.ca.shared.global [%0], [%1], 16;" :: "r"(dst), "l"(src));
}
__device__ __forceinline__ void cpa_commit() {
    asm volatile("cp.async.commit_group;" ::: "memory");
}
__device__ __forceinline__ void cpa_wait0() {
    asm volatile("cp.async.wait_group 0;" ::: "memory");
}

// ================= dummy (ncu capture alignment: capture = 4th launch) =====
__global__ void k_nop() {}

// ================= fold Q into Wk =================
__global__ void k_precompP(const float* __restrict__ Q,
                           const float* __restrict__ Wk,
                           const float* __restrict__ bk) {
    int m = blockIdx.x;            // 0..207
    int c = threadIdx.x;           // 0..255
    int hk = m / 13;
    const float* qp = Q + m * 4;
    float q0 = qp[0], q1 = qp[1], q2 = qp[2], q3 = qp[3];
    float* dst = g_P + (size_t)c * 3328 + m * 16;
    #pragma unroll
    for (int a = 0; a < 13; ++a) {
        const float* w = Wk + (size_t)(a * 64 + hk * 4) * 256 + c;
        float s = q0 * w[0] + q1 * w[256] + q2 * w[512] + q3 * w[768];
        dst[a] = 0.5f * s;
    }
    dst[13] = dst[14] = dst[15] = 0.f;
    if (c < 16) {
        float v = 0.f;
        if (c < 13) {
            const float* bb = bk + c * 64 + hk * 4;
            v = 0.5f * (q0 * bb[0] + q1 * bb[1] + q2 * bb[2] + q3 * bb[3]);
        }
        g_Pb[m * 16 + c] = v;
    }
}

// ================= fold BN into W1, transpose =================
__global__ void k_foldW1(const float* __restrict__ W1, const float* __restrict__ b1,
                         const float* __restrict__ bnw, const float* __restrict__ bnb,
                         const float* __restrict__ bnrm, const float* __restrict__ bnrv) {
    int f = blockIdx.x;    // 0..127
    int c = threadIdx.x;   // 0..255
    float s = bnw[f] * rsqrtf(bnrv[f] + EPSF);
    g_W1T[c * 128 + f] = W1[f * 256 + c] * s;
    if (c == 0) g_bf[f] = b1[f] * s + bnb[f] - bnrm[f] * s;
}

// ================= fused conv + GN + logits + softmax + AV =================
// smem (floats):
//   vT2: 128 rows (channel-pair cp) x 132 floats. Unit [cp][tp] = 16B:
//        { v[2cp][2tp], v[2cp][2tp+1], v[2cp+1][2tp], v[2cp+1][2tp+1] }
//        tp 0..29 real, tp 30..31 zeroed. Row = 32 tp * 4 floats + 4 pad = 132.
//   Pch: 2 bufs x 8c x 128 cols
//   Ms : 32 rows x 256 (t-pair major, ull per col); pbuf aliased on rows 30-31,
//        sx aliased on Ms (pre-GEMM only).
#define VT2_STRIDE 132
#define VT2_OFF  0                               // 128*132 = 16896
#define PCH_OFF  (VT2_OFF + 128*VT2_STRIDE)      // 2048
#define MS_OFF   (PCH_OFF + 2048)                // 8192
#define PB_OFF   (MS_OFF + 30*256)               // rows 30-31
#define SMEM_ATT_FLOATS (MS_OFF + 32*256)        // 27136
#define SMEM_ATT_BYTES  (SMEM_ATT_FLOATS * 4)    // 108,544 B -> 2 CTAs/SM

__global__ void __launch_bounds__(256, 2) k_attention(
    const float* __restrict__ x, const float* __restrict__ Wc,
    const float* __restrict__ bc, const float* __restrict__ ginw,
    const float* __restrict__ ginb) {
    extern __shared__ float sm[];
    float* vT2  = sm + VT2_OFF;
    float* Pch  = sm + PCH_OFF;
    float* MsF  = sm + MS_OFF;
    float* pbuf = sm + PB_OFF;
    float* sx   = sm + MS_OFF;      // aliased: only used before GEMM
    const int tid = threadIdx.x;
    const int b = blockIdx.x;

    // stage x[b] (600 floats)
    for (int i = tid; i < 150; i += 256)
        ((float4*)sx)[i] = ((const float4*)(x + (size_t)b * 600))[i];
    __syncthreads();

    // ---- conv1x1 + GroupNorm(16 groups), thread = channel ----
    {
        const int c = tid;
        float wr[10];
        #pragma unroll
        for (int i = 0; i < 10; ++i) wr[i] = Wc[c * 10 + i];
        const float bb = bc[c];
        float s1 = 0.f, s2 = 0.f;
        float* vrow2 = vT2 + (c >> 1) * VT2_STRIDE + (c & 1) * 2;
        #pragma unroll 6
        for (int tp = 0; tp < 30; ++tp) {
            const float* xr0 = sx + (2 * tp) * 10;
            float h0 = bb, h1 = bb;
            #pragma unroll
            for (int i = 0; i < 10; ++i) {
                h0 = fmaf(wr[i], xr0[i], h0);
                h1 = fmaf(wr[i], xr0[10 + i], h1);
            }
            *(float2*)(vrow2 + tp * 4) = make_float2(h0, h1);
            s1 += h0 + h1;
            s2 = fmaf(h0, h0, s2);
            s2 = fmaf(h1, h1, s2);
        }
        #pragma unroll
        for (int o = 8; o; o >>= 1) {
            s1 += __shfl_xor_sync(0xffffffffu, s1, o);
            s2 += __shfl_xor_sync(0xffffffffu, s2, o);
        }
        float mean = s1 * (1.f / 960.f);
        float var = s2 * (1.f / 960.f) - mean * mean;
        float sc = ginw[c] * rsqrtf(var + EPSF);
        float sh = ginb[c] - mean * sc;
        ull scl = dup2(sc), shf = dup2(sh);
        #pragma unroll 6
        for (int tp = 0; tp < 30; ++tp) {
            ull v = *(ull*)(vrow2 + tp * 4);
            *(ull*)(vrow2 + tp * 4) = fma2(v, scl, shf);
        }
        *(float2*)(vrow2 + 30 * 4) = make_float2(0.f, 0.f);
        *(float2*)(vrow2 + 31 * 4) = make_float2(0.f, 0.f);
    }
    __syncthreads();   // vT2 ready; sx fully consumed before Ms/Pch writes

    const int e0 = (b * 13) >> 10;
    const int e12 = (b * 13 + 12) >> 10;
    const int nchunks = (e0 == e12) ? 2 : 4;
    const int w = tid >> 5;
    const int lane = tid & 31;

    // staging coords: one float4 per thread per 8-c step
    const int sc_ = tid >> 5;          // c within step (0..7)
    const int ss_ = (tid >> 2) & 7;    // col group (16 cols)
    const int sf_ = tid & 3;           // float4 within group
    const unsigned pch_b = (unsigned)__cvta_generic_to_shared(Pch) +
                           (unsigned)((sc_ * 128 + ss_ * 16 + sf_ * 4) * 4);

    for (int chunk = 0; chunk < nchunks; ++chunk) {
        const int S = chunk * 8 + ss_;
        const int mm = (S < 16) ? (S * 13 + e0) : ((S - 16) * 13 + e0 + 1);
        const float* src0 = g_P + (size_t)sc_ * 3328 + mm * 16 + sf_ * 4;

        ull acc[4][4];
        #pragma unroll
        for (int i = 0; i < 4; ++i)
            #pragma unroll
            for (int j = 0; j < 4; ++j) acc[i][j] = 0ull;

        // prologue: prefetch step 0
        cpa16(pch_b, src0);
        cpa_commit();

        for (int step = 0; step < 32; ++step) {
            cpa_wait0();
            __syncthreads();
            if (step + 1 < 32) {
                cpa16(pch_b + ((step + 1) & 1) * 4096u,
                      src0 + (size_t)(step + 1) * 26624);
                cpa_commit();
            }
            const float* Pbuf = Pch + (step & 1) * 1024;
            const int cpb = step * 4;       // channel-pair base
            #pragma unroll
            for (int cpi = 0; cpi < 4; ++cpi) {
                const float* vb = vT2 + (cpb + cpi) * VT2_STRIDE + w * 16;
                ulonglong2 t0 = *(const ulonglong2*)(vb);        // .x even-c, .y odd-c (tp0)
                ulonglong2 t1 = *(const ulonglong2*)(vb + 4);
                ulonglong2 t2 = *(const ulonglong2*)(vb + 8);
                ulonglong2 t3 = *(const ulonglong2*)(vb + 12);
                float4 pe = *(const float4*)(Pbuf + (2 * cpi) * 128 + lane * 4);
                float4 po = *(const float4*)(Pbuf + (2 * cpi + 1) * 128 + lane * 4);
                ull pe0 = dup2(pe.x), pe1 = dup2(pe.y), pe2 = dup2(pe.z), pe3 = dup2(pe.w);
                ull po0 = dup2(po.x), po1 = dup2(po.y), po2 = dup2(po.z), po3 = dup2(po.w);
                acc[0][0] = fma2(t0.x, pe0, acc[0][0]);
                acc[0][1] = fma2(t0.x, pe1, acc[0][1]);
                acc[0][2] = fma2(t0.x, pe2, acc[0][2]);
                acc[0][3] = fma2(t0.x, pe3, acc[0][3]);
                acc[1][0] = fma2(t1.x, pe0, acc[1][0]);
                acc[1][1] = fma2(t1.x, pe1, acc[1][1]);
                acc[1][2] = fma2(t1.x, pe2, acc[1][2]);
                acc[1][3] = fma2(t1.x, pe3, acc[1][3]);
                acc[2][0] = fma2(t2.x, pe0, acc[2][0]);
                acc[2][1] = fma2(t2.x, pe1, acc[2][1]);
                acc[2][2] = fma2(t2.x, pe2, acc[2][2]);
                acc[2][3] = fma2(t2.x, pe3, acc[2][3]);
                acc[3][0] = fma2(t3.x, pe0, acc[3][0]);
                acc[3][1] = fma2(t3.x, pe1, acc[3][1]);
                acc[3][2] = fma2(t3.x, pe2, acc[3][2]);
                acc[3][3] = fma2(t3.x, pe3, acc[3][3]);
                acc[0][0] = fma2(t0.y, po0, acc[0][0]);
                acc[0][1] = fma2(t0.y, po1, acc[0][1]);
                acc[0][2] = fma2(t0.y, po2, acc[0][2]);
                acc[0][3] = fma2(t0.y, po3, acc[0][3]);
                acc[1][0] = fma2(t1.y, po0, acc[1][0]);
                acc[1][1] = fma2(t1.y, po1, acc[1][1]);
                acc[1][2] = fma2(t1.y, po2, acc[1][2]);
                acc[1][3] = fma2(t1.y, po3, acc[1][3]);
                acc[2][0] = fma2(t2.y, po0, acc[2][0]);
                acc[2][1] = fma2(t2.y, po1, acc[2][1]);
                acc[2][2] = fma2(t2.y, po2, acc[2][2]);
                acc[2][3] = fma2(t2.y, po3, acc[2][3]);
                acc[3][0] = fma2(t3.y, po0, acc[3][0]);
                acc[3][1] = fma2(t3.y, po1, acc[3][1]);
                acc[3][2] = fma2(t3.y, po2, acc[3][2]);
                acc[3][3] = fma2(t3.y, po3, acc[3][3]);
            }
        }

        // write Ms (rows = t-pairs, 256-float rows), chunk-local cols 0..127
        #pragma unroll
        for (int i = 0; i < 4; ++i) {
            int tp = w * 4 + i;
            *(ulonglong2*)(MsF + tp * 256 + lane * 8) = make_ulonglong2(acc[i][0], acc[i][1]);
            *(ulonglong2*)(MsF + tp * 256 + lane * 8 + 4) = make_ulonglong2(acc[i][2], acc[i][3]);
        }
        __syncthreads();

        // ---- epilogue for this chunk: warp w owns hk = (chunk&1)*8 + w ----
        const int ec = e0 + (chunk >> 1);
        const int hk = ((chunk & 1) << 3) + w;
        for (int j = 0; j < 13; ++j) {
            int e = (b * 13 + j) >> 10;
            if (e != ec) continue;
            int m = hk * 13 + e;
            int val = j * 240 + lane * 4;
            int t = val / 52;
            int a = (val - t * 52) >> 2;
            float l1 = MsF[2 * ((t >> 1) * 128 + w * 16 + a) + (t & 1)] + g_Pb[m * 16 + a];
            float l2 = -1e30f;
            if (lane < 28) {
                int val2 = val + 128;
                int t2 = val2 / 52;
                int a2 = (val2 - t2 * 52) >> 2;
                l2 = MsF[2 * ((t2 >> 1) * 128 + w * 16 + a2) + (t2 & 1)] + g_Pb[m * 16 + a2];
            }
            float mx = fmaxf(l1, l2);
            #pragma unroll
            for (int o = 16; o; o >>= 1) mx = fmaxf(mx, __shfl_xor_sync(0xffffffffu, mx, o));
            float x1 = __expf(l1 - mx);
            float x2 = (lane < 28) ? __expf(l2 - mx) : 0.f;
            float sum = x1 + x2;
            #pragma unroll
            for (int o = 16; o; o >>= 1) sum += __shfl_xor_sync(0xffffffffu, sum, o);
            float inv = 1.f / sum;
            pbuf[w * 64 + lane] = x1 * inv;
            if (lane < 28) pbuf[w * 64 + 32 + lane] = x2 * inv;
            __syncwarp();
            // AV: lanes 0..15 sum t 0..29, lanes 16..31 sum t 30..59
            int dh = lane & 15;
            int toff = (lane >> 4) * 30;
            int c = hk * 16 + dh;
            const float* vcol2 = vT2 + (c >> 1) * VT2_STRIDE + (c & 1) * 2;
            const float* pb = pbuf + w * 64 + toff;
            float a0 = 0.f, a1 = 0.f;
            #pragma unroll
            for (int tt = 0; tt < 15; ++tt) {
                int tg0 = toff + tt;
                int tg1 = toff + tt + 15;
                a0 = fmaf(pb[tt], vcol2[(tg0 >> 1) * 4 + (tg0 & 1)], a0);
                a1 = fmaf(pb[tt + 15], vcol2[(tg1 >> 1) * 4 + (tg1 & 1)], a1);
            }
            float acv = a0 + a1;
            acv += __shfl_xor_sync(0xffffffffu, acv, 16);
            if (lane < 16) {
                int bq = (b * 13 + j) & 1023;
                g_att[(size_t)((m >> 4) * 1024 + bq) * 256 + ((m & 15) << 4) + dh] = acv;
            }
            __syncwarp();
        }
        __syncthreads();   // Ms/pbuf reads done before next chunk overwrites
    }
}

// ================= MLP + BN + ReLU + GroupNorm + permute =================
// 104 blocks x 128 rows (round-3 proven version, 37.4 us)
#define SO_OFF   0                          // [128][260]
#define SWC_OFF  (128*260)                  // [64][132]
#define SBF_OFF  (SWC_OFF + 64*132)
#define SGW_OFF  (SBF_OFF + 128)
#define SGB_OFF  (SGW_OFF + 128)
#define SMEM_MLP_FLOATS (SGB_OFF + 128)
#define SMEM_MLP_BYTES  (SMEM_MLP_FLOATS * 4)

__global__ void __launch_bounds__(256, 1) k_mlp(const float* __restrict__ gow,
                                                const float* __restrict__ gob,
                                                float* __restrict__ out) {
    extern __shared__ float sm[];
    float* sO  = sm + SO_OFF;
    float* sW  = sm + SWC_OFF;
    float* sBF = sm + SBF_OFF;
    float* sGW = sm + SGW_OFF;
    float* sGB = sm + SGB_OFF;
    const int tid = threadIdx.x;
    const int row0 = blockIdx.x * 128;

    for (int q = tid; q < 8192; q += 256) {
        int row = q >> 6, c4 = q & 63;
        *(float4*)(sO + row * 260 + c4 * 4) =
            *(const float4*)(g_att + (size_t)(row0 + row) * 256 + c4 * 4);
    }
    if (tid < 128) { sBF[tid] = g_bf[tid]; sGW[tid] = gow[tid]; sGB[tid] = gob[tid]; }

    const int rq = tid >> 3;       // 0..31
    const int fg = tid & 7;        // f = 16k + fg*2 + {0,1}
    ull acc[4][8];
    #pragma unroll
    for (int i = 0; i < 4; ++i)
        #pragma unroll
        for (int k = 0; k < 8; ++k) acc[i][k] = 0ull;

    for (int cc = 0; cc < 4; ++cc) {
        __syncthreads();
        for (int q = tid; q < 2048; q += 256) {
            int c = q >> 5, f4 = q & 31;
            *(float4*)(sW + c * 132 + f4 * 4) =
                *(const float4*)(g_W1T + (size_t)(cc * 64 + c) * 128 + f4 * 4);
        }
        __syncthreads();
        #pragma unroll 4
        for (int c = 0; c < 64; ++c) {
            const float* wr = sW + c * 132 + fg * 2;
            ull wv[8];
            #pragma unroll
            for (int k = 0; k < 8; ++k) wv[k] = *(const ull*)(wr + 16 * k);
            int cg = cc * 64 + c;
            #pragma unroll
            for (int i = 0; i < 4; ++i) {
                ull od = dup2(sO[(rq + 32 * i) * 260 + cg]);
                #pragma unroll
                for (int k = 0; k < 8; ++k)
                    acc[i][k] = fma2(od, wv[k], acc[i][k]);
            }
        }
    }

    #pragma unroll
    for (int i = 0; i < 4; ++i) {
        int r = row0 + rq + 32 * i;
        float* orow_out = out + (size_t)((r & 1023) * 13 + (r >> 10)) * 128;
        #pragma unroll
        for (int k = 0; k < 8; ++k) {
            int f = 16 * k + fg * 2;
            float y0 = fmaxf(lo32(acc[i][k]) + sBF[f], 0.f);
            float y1 = fmaxf(hi32(acc[i][k]) + sBF[f + 1], 0.f);
            float s = y0 + y1;
            float s2 = y0 * y0 + y1 * y1;
            s  += __shfl_xor_sync(0xffffffffu, s, 1);
            s2 += __shfl_xor_sync(0xffffffffu, s2, 1);
            s  += __shfl_xor_sync(0xffffffffu, s, 2);
            s2 += __shfl_xor_sync(0xffffffffu, s2, 2);
            float mean = s * 0.125f;
            float var = s2 * 0.125f - mean * mean;
            float sc = rsqrtf(var + EPSF);
            float o0 = (y0 - mean) * sc * sGW[f] + sGB[f];
            float o1 = (y1 - mean) * sc * sGW[f + 1] + sGB[f + 1];
            *(float2*)(orow_out + f) = make_float2(o0, o1);
        }
    }
}

// ================= launch =================
extern "C" void kernel_launch(void* const* d_in, const int* in_sizes, int n_in,
                              void* d_out, int out_size) {
    (void)in_sizes; (void)n_in; (void)out_size;
    const float* x    = (const float*)d_in[0];
    const float* Wc   = (const float*)d_in[1];
    const float* bc   = (const float*)d_in[2];
    const float* ginw = (const float*)d_in[3];
    const float* ginb = (const float*)d_in[4];
    const float* Q    = (const float*)d_in[5];
    const float* Wk   = (const float*)d_in[6];
    const float* bk   = (const float*)d_in[7];
    const float* W1   = (const float*)d_in[8];
    const float* b1   = (const float*)d_in[9];
    const float* bnw  = (const float*)d_in[10];
    const float* bnb  = (const float*)d_in[11];
    const float* bnrm = (const float*)d_in[12];
    const float* bnrv = (const float*)d_in[13];
    const float* gow  = (const float*)d_in[14];
    const float* gob  = (const float*)d_in[15];
    float* out = (float*)d_out;

    cudaFuncSetAttribute(k_attention, cudaFuncAttributeMaxDynamicSharedMemorySize, SMEM_ATT_BYTES);
    cudaFuncSetAttribute(k_mlp, cudaFuncAttributeMaxDynamicSharedMemorySize, SMEM_MLP_BYTES);

    k_precompP<<<208, 256>>>(Q, Wk, bk);                       // launch 1
    k_foldW1<<<128, 256>>>(W1, b1, bnw, bnb, bnrm, bnrv);      // launch 2
    k_nop<<<1, 32>>>();                                        // launch 3
    k_attention<<<1024, 256, SMEM_ATT_BYTES>>>(x, Wc, bc, ginw, ginb);  // launch 4 (ncu target)
    k_mlp<<<104, 256, SMEM_MLP_BYTES>>>(gow, gob, out);        // launch 5
}

// round 10
// speedup vs baseline: 1.0062x; 1.0062x over previous
#include <cuda_runtime.h>
#include <cuda_bf16.h>
#include <cstdint>

typedef unsigned long long ull;

#define EPSF 1e-5f

// ---------------- scratch ----------------
__device__ float g_P[(size_t)256 * 208 * 16];   // [c][m][a16], 0.5 folded
__device__ float g_Pb[208 * 16];                // [m][a16], 0.5 folded
__device__ float g_W1T[256 * 128];              // [c][f], BN-scale folded
__device__ float g_bf[128];                     // folded bias
__device__ float g_att[(size_t)13312 * 256];    // attention out, row = a*1024 + b

// ---------------- helpers ----------------
__device__ __forceinline__ ull fma2(ull a, ull b, ull c) {
    ull d;
    asm("fma.rn.f32x2 %0, %1, %2, %3;" : "=l"(d) : "l"(a), "l"(b), "l"(c));
    return d;
}
__device__ __forceinline__ ull add2(ull a, ull b) {
    ull d;
    asm("add.rn.f32x2 %0, %1, %2;" : "=l"(d) : "l"(a), "l"(b));
    return d;
}
__device__ __forceinline__ ull dup2(float v) {
    ull d; unsigned r = __float_as_uint(v);
    asm("mov.b64 %0, {%1, %1};" : "=l"(d) : "r"(r));
    return d;
}
__device__ __forceinline__ float lo32(ull a) { return __uint_as_float((unsigned)(a & 0xffffffffull)); }
__device__ __forceinline__ float hi32(ull a) { return __uint_as_float((unsigned)(a >> 32)); }

__device__ __forceinline__ void cpa16(unsigned dst, const void* src) {
    asm volatile("cp.async.ca.shared.global [%0], [%1], 16;" :: "r"(dst), "l"(src));
}
__device__ __forceinline__ void cpa_commit() {
    asm volatile("cp.async.commit_group;" ::: "memory");
}
__device__ __forceinline__ void cpa_wait0() {
    asm volatile("cp.async.wait_group 0;" ::: "memory");
}

// ================= dummy (ncu capture alignment: capture = 4th launch) =====
__global__ void k_nop() {}

// ================= fold Q into Wk =================
__global__ void k_precompP(const float* __restrict__ Q,
                           const float* __restrict__ Wk,
                           const float* __restrict__ bk) {
    int m = blockIdx.x;            // 0..207
    int c = threadIdx.x;           // 0..255
    int hk = m / 13;
    const float* qp = Q + m * 4;
    float q0 = qp[0], q1 = qp[1], q2 = qp[2], q3 = qp[3];
    float* dst = g_P + (size_t)c * 3328 + m * 16;
    #pragma unroll
    for (int a = 0; a < 13; ++a) {
        const float* w = Wk + (size_t)(a * 64 + hk * 4) * 256 + c;
        float s = q0 * w[0] + q1 * w[256] + q2 * w[512] + q3 * w[768];
        dst[a] = 0.5f * s;
    }
    dst[13] = dst[14] = dst[15] = 0.f;
    if (c < 16) {
        float v = 0.f;
        if (c < 13) {
            const float* bb = bk + c * 64 + hk * 4;
            v = 0.5f * (q0 * bb[0] + q1 * bb[1] + q2 * bb[2] + q3 * bb[3]);
        }
        g_Pb[m * 16 + c] = v;
    }
}

// ================= fold BN into W1, transpose =================
__global__ void k_foldW1(const float* __restrict__ W1, const float* __restrict__ b1,
                         const float* __restrict__ bnw, const float* __restrict__ bnb,
                         const float* __restrict__ bnrm, const float* __restrict__ bnrv) {
    int f = blockIdx.x;    // 0..127
    int c = threadIdx.x;   // 0..255
    float s = bnw[f] * rsqrtf(bnrv[f] + EPSF);
    g_W1T[c * 128 + f] = W1[f * 256 + c] * s;
    if (c == 0) g_bf[f] = b1[f] * s + bnb[f] - bnrm[f] * s;
}

// ================= fused conv + GN + logits + softmax + AV =================
// smem (floats): vT [256][68] | Pch 2 bufs x 8c x 128 | Ms 32 rows x 256
// pbuf aliased onto Ms rows 30-31; sx aliased onto Ms (pre-GEMM only).
// Total = 17408 + 2048 + 8192 = 27648 floats = 110,592 B -> 2 CTAs/SM
#define VT_STRIDE 68
#define VT_OFF   0                               // 17408
#define PCH_OFF  (VT_OFF + 256*VT_STRIDE)        // 2048
#define MS_OFF   (PCH_OFF + 2048)                // 8192
#define PB_OFF   (MS_OFF + 30*256)               // rows 30-31
#define SMEM_ATT_FLOATS (MS_OFF + 32*256)        // 27648
#define SMEM_ATT_BYTES  (SMEM_ATT_FLOATS * 4)    // 110,592 B

__global__ void __launch_bounds__(256, 2) k_attention(
    const float* __restrict__ x, const float* __restrict__ Wc,
    const float* __restrict__ bc, const float* __restrict__ ginw,
    const float* __restrict__ ginb) {
    extern __shared__ float sm[];
    float* vTf  = sm + VT_OFF;
    float* Pch  = sm + PCH_OFF;
    float* MsF  = sm + MS_OFF;
    float* pbuf = sm + PB_OFF;
    float* sx   = sm + MS_OFF;      // aliased: only used before GEMM
    const int tid = threadIdx.x;
    const int b = blockIdx.x;

    // stage x[b] (600 floats)
    for (int i = tid; i < 150; i += 256)
        ((float4*)sx)[i] = ((const float4*)(x + (size_t)b * 600))[i];
    __syncthreads();

    // ---- conv1x1 + GroupNorm(16 groups), thread = channel ----
    {
        const int c = tid;
        float wr[10];
        #pragma unroll
        for (int i = 0; i < 10; ++i) wr[i] = Wc[c * 10 + i];
        const float bb = bc[c];
        float s1 = 0.f, s2 = 0.f;
        float* vrow = vTf + c * VT_STRIDE;
        #pragma unroll 4
        for (int t = 0; t < 60; ++t) {
            const float* xr = sx + t * 10;
            float h = bb;
            #pragma unroll
            for (int i = 0; i < 10; ++i) h = fmaf(wr[i], xr[i], h);
            vrow[t] = h; s1 += h; s2 = fmaf(h, h, s2);
        }
        #pragma unroll
        for (int o = 8; o; o >>= 1) {
            s1 += __shfl_xor_sync(0xffffffffu, s1, o);
            s2 += __shfl_xor_sync(0xffffffffu, s2, o);
        }
        float mean = s1 * (1.f / 960.f);
        float var = s2 * (1.f / 960.f) - mean * mean;
        float sc = ginw[c] * rsqrtf(var + EPSF);
        float sh = ginb[c] - mean * sc;
        #pragma unroll 4
        for (int t = 0; t < 60; ++t) vrow[t] = fmaf(vrow[t], sc, sh);
        #pragma unroll
        for (int t = 60; t < 68; ++t) vrow[t] = 0.f;
    }
    __syncthreads();   // vT ready; sx fully consumed before Ms/Pch writes

    const int e0 = (b * 13) >> 10;
    const int e12 = (b * 13 + 12) >> 10;
    const int nchunks = (e0 == e12) ? 2 : 4;
    const int w = tid >> 5;
    const int lane = tid & 31;
    const int tg = w & 3;          // t-group: t = tg*16 .. +16
    const int half = w >> 2;       // channel half: c = half*128 .. +128

    // staging coords: one float4 per thread per step (8 channels: 4 half0 + 4 half1)
    const int sc_ = tid >> 5;          // Pch row 0..7
    const int ss_ = (tid >> 2) & 7;    // col group (16 cols)
    const int sf_ = tid & 3;           // float4 within group
    const unsigned pch_b = (unsigned)__cvta_generic_to_shared(Pch) +
                           (unsigned)((sc_ * 128 + ss_ * 16 + sf_ * 4) * 4);
    const int cbase_ = (sc_ >> 2) * 128 + (sc_ & 3);   // channel for step 0

    for (int chunk = 0; chunk < nchunks; ++chunk) {
        const int S = chunk * 8 + ss_;
        const int mm = (S < 16) ? (S * 13 + e0) : ((S - 16) * 13 + e0 + 1);
        const float* src0 = g_P + (size_t)cbase_ * 3328 + mm * 16 + sf_ * 4;

        ull acc[8][4];
        #pragma unroll
        for (int i = 0; i < 8; ++i)
            #pragma unroll
            for (int j = 0; j < 4; ++j) acc[i][j] = 0ull;

        // prologue: prefetch step 0
        cpa16(pch_b, src0);
        cpa_commit();

        for (int step = 0; step < 32; ++step) {
            cpa_wait0();
            __syncthreads();
            if (step + 1 < 32) {
                cpa16(pch_b + ((step + 1) & 1) * 4096u,
                      src0 + (size_t)(step + 1) * 13312);   // +4 channels
                cpa_commit();
            }
            const float* Pbuf = Pch + (step & 1) * 1024;
            const int cg0 = half * 128 + step * 4;
            #pragma unroll
            for (int kk = 0; kk < 4; ++kk) {
                const float* vb = vTf + (cg0 + kk) * VT_STRIDE + tg * 16;
                ulonglong2 u01 = *(const ulonglong2*)(vb);
                ulonglong2 u23 = *(const ulonglong2*)(vb + 4);
                ulonglong2 u45 = *(const ulonglong2*)(vb + 8);
                ulonglong2 u67 = *(const ulonglong2*)(vb + 12);
                float4 pp = *(const float4*)(Pbuf + (half * 4 + kk) * 128 + lane * 4);
                ull p0 = dup2(pp.x), p1 = dup2(pp.y), p2 = dup2(pp.z), p3 = dup2(pp.w);
                acc[0][0] = fma2(u01.x, p0, acc[0][0]);
                acc[0][1] = fma2(u01.x, p1, acc[0][1]);
                acc[0][2] = fma2(u01.x, p2, acc[0][2]);
                acc[0][3] = fma2(u01.x, p3, acc[0][3]);
                acc[1][0] = fma2(u01.y, p0, acc[1][0]);
                acc[1][1] = fma2(u01.y, p1, acc[1][1]);
                acc[1][2] = fma2(u01.y, p2, acc[1][2]);
                acc[1][3] = fma2(u01.y, p3, acc[1][3]);
                acc[2][0] = fma2(u23.x, p0, acc[2][0]);
                acc[2][1] = fma2(u23.x, p1, acc[2][1]);
                acc[2][2] = fma2(u23.x, p2, acc[2][2]);
                acc[2][3] = fma2(u23.x, p3, acc[2][3]);
                acc[3][0] = fma2(u23.y, p0, acc[3][0]);
                acc[3][1] = fma2(u23.y, p1, acc[3][1]);
                acc[3][2] = fma2(u23.y, p2, acc[3][2]);
                acc[3][3] = fma2(u23.y, p3, acc[3][3]);
                acc[4][0] = fma2(u45.x, p0, acc[4][0]);
                acc[4][1] = fma2(u45.x, p1, acc[4][1]);
                acc[4][2] = fma2(u45.x, p2, acc[4][2]);
                acc[4][3] = fma2(u45.x, p3, acc[4][3]);
                acc[5][0] = fma2(u45.y, p0, acc[5][0]);
                acc[5][1] = fma2(u45.y, p1, acc[5][1]);
                acc[5][2] = fma2(u45.y, p2, acc[5][2]);
                acc[5][3] = fma2(u45.y, p3, acc[5][3]);
                acc[6][0] = fma2(u67.x, p0, acc[6][0]);
                acc[6][1] = fma2(u67.x, p1, acc[6][1]);
                acc[6][2] = fma2(u67.x, p2, acc[6][2]);
                acc[6][3] = fma2(u67.x, p3, acc[6][3]);
                acc[7][0] = fma2(u67.y, p0, acc[7][0]);
                acc[7][1] = fma2(u67.y, p1, acc[7][1]);
                acc[7][2] = fma2(u67.y, p2, acc[7][2]);
                acc[7][3] = fma2(u67.y, p3, acc[7][3]);
            }
        }

        // half 0 writes Ms (rows = t-pairs tp = tg*8+i)
        if (half == 0) {
            #pragma unroll
            for (int i = 0; i < 8; ++i) {
                int tp = tg * 8 + i;
                *(ulonglong2*)(MsF + tp * 256 + lane * 8) = make_ulonglong2(acc[i][0], acc[i][1]);
                *(ulonglong2*)(MsF + tp * 256 + lane * 8 + 4) = make_ulonglong2(acc[i][2], acc[i][3]);
            }
        }
        __syncthreads();
        // half 1 accumulates into Ms
        if (half == 1) {
            #pragma unroll
            for (int i = 0; i < 8; ++i) {
                int tp = tg * 8 + i;
                ulonglong2 m0 = *(ulonglong2*)(MsF + tp * 256 + lane * 8);
                ulonglong2 m1 = *(ulonglong2*)(MsF + tp * 256 + lane * 8 + 4);
                m0.x = add2(m0.x, acc[i][0]);
                m0.y = add2(m0.y, acc[i][1]);
                m1.x = add2(m1.x, acc[i][2]);
                m1.y = add2(m1.y, acc[i][3]);
                *(ulonglong2*)(MsF + tp * 256 + lane * 8) = m0;
                *(ulonglong2*)(MsF + tp * 256 + lane * 8 + 4) = m1;
            }
        }
        __syncthreads();

        // ---- epilogue for this chunk: warp w owns hk = (chunk&1)*8 + w ----
        const int ec = e0 + (chunk >> 1);
        const int hk = ((chunk & 1) << 3) + w;
        for (int j = 0; j < 13; ++j) {
            int e = (b * 13 + j) >> 10;
            if (e != ec) continue;
            int m = hk * 13 + e;
            int val = j * 240 + lane * 4;
            int t = val / 52;
            int a = (val - t * 52) >> 2;
            float l1 = MsF[2 * ((t >> 1) * 128 + w * 16 + a) + (t & 1)] + g_Pb[m * 16 + a];
            float l2 = -1e30f;
            if (lane < 28) {
                int val2 = val + 128;
                int t2 = val2 / 52;
                int a2 = (val2 - t2 * 52) >> 2;
                l2 = MsF[2 * ((t2 >> 1) * 128 + w * 16 + a2) + (t2 & 1)] + g_Pb[m * 16 + a2];
            }
            float mx = fmaxf(l1, l2);
            #pragma unroll
            for (int o = 16; o; o >>= 1) mx = fmaxf(mx, __shfl_xor_sync(0xffffffffu, mx, o));
            float x1 = __expf(l1 - mx);
            float x2 = (lane < 28) ? __expf(l2 - mx) : 0.f;
            float sum = x1 + x2;
            #pragma unroll
            for (int o = 16; o; o >>= 1) sum += __shfl_xor_sync(0xffffffffu, sum, o);
            float inv = 1.f / sum;
            pbuf[w * 64 + lane] = x1 * inv;
            if (lane < 28) pbuf[w * 64 + 32 + lane] = x2 * inv;
            __syncwarp();
            // AV: lanes 0..15 sum t 0..29, lanes 16..31 sum t 30..59
            int dh = lane & 15;
            int toff = (lane >> 4) * 30;
            const float* vcol = vTf + (hk * 16 + dh) * VT_STRIDE + toff;
            const float* pb = pbuf + w * 64 + toff;
            float a0 = 0.f, a1 = 0.f;
            #pragma unroll
            for (int tt = 0; tt < 15; ++tt) {
                a0 = fmaf(pb[tt], vcol[tt], a0);
                a1 = fmaf(pb[tt + 15], vcol[tt + 15], a1);
            }
            float acv = a0 + a1;
            acv += __shfl_xor_sync(0xffffffffu, acv, 16);
            if (lane < 16) {
                int bq = (b * 13 + j) & 1023;
                g_att[(size_t)((m >> 4) * 1024 + bq) * 256 + ((m & 15) << 4) + dh] = acv;
            }
            __syncwarp();
        }
        __syncthreads();   // Ms/pbuf reads done before next chunk overwrites
    }
}

// ================= MLP + BN + ReLU + GroupNorm + permute =================
// 104 blocks x 128 rows (round-3 proven version, 37.4 us)
#define SO_OFF   0                          // [128][260]
#define SWC_OFF  (128*260)                  // [64][132]
#define SBF_OFF  (SWC_OFF + 64*132)
#define SGW_OFF  (SBF_OFF + 128)
#define SGB_OFF  (SGW_OFF + 128)
#define SMEM_MLP_FLOATS (SGB_OFF + 128)
#define SMEM_MLP_BYTES  (SMEM_MLP_FLOATS * 4)

__global__ void __launch_bounds__(256, 1) k_mlp(const float* __restrict__ gow,
                                                const float* __restrict__ gob,
                                                float* __restrict__ out) {
    extern __shared__ float sm[];
    float* sO  = sm + SO_OFF;
    float* sW  = sm + SWC_OFF;
    float* sBF = sm + SBF_OFF;
    float* sGW = sm + SGW_OFF;
    float* sGB = sm + SGB_OFF;
    const int tid = threadIdx.x;
    const int row0 = blockIdx.x * 128;

    for (int q = tid; q < 8192; q += 256) {
        int row = q >> 6, c4 = q & 63;
        *(float4*)(sO + row * 260 + c4 * 4) =
            *(const float4*)(g_att + (size_t)(row0 + row) * 256 + c4 * 4);
    }
    if (tid < 128) { sBF[tid] = g_bf[tid]; sGW[tid] = gow[tid]; sGB[tid] = gob[tid]; }

    const int rq = tid >> 3;       // 0..31
    const int fg = tid & 7;        // f = 16k + fg*2 + {0,1}
    ull acc[4][8];
    #pragma unroll
    for (int i = 0; i < 4; ++i)
        #pragma unroll
        for (int k = 0; k < 8; ++k) acc[i][k] = 0ull;

    for (int cc = 0; cc < 4; ++cc) {
        __syncthreads();
        for (int q = tid; q < 2048; q += 256) {
            int c = q >> 5, f4 = q & 31;
            *(float4*)(sW + c * 132 + f4 * 4) =
                *(const float4*)(g_W1T + (size_t)(cc * 64 + c) * 128 + f4 * 4);
        }
        __syncthreads();
        #pragma unroll 4
        for (int c = 0; c < 64; ++c) {
            const float* wr = sW + c * 132 + fg * 2;
            ull wv[8];
            #pragma unroll
            for (int k = 0; k < 8; ++k) wv[k] = *(const ull*)(wr + 16 * k);
            int cg = cc * 64 + c;
            #pragma unroll
            for (int i = 0; i < 4; ++i) {
                ull od = dup2(sO[(rq + 32 * i) * 260 + cg]);
                #pragma unroll
                for (int k = 0; k < 8; ++k)
                    acc[i][k] = fma2(od, wv[k], acc[i][k]);
            }
        }
    }

    #pragma unroll
    for (int i = 0; i < 4; ++i) {
        int r = row0 + rq + 32 * i;
        float* orow_out = out + (size_t)((r & 1023) * 13 + (r >> 10)) * 128;
        #pragma unroll
        for (int k = 0; k < 8; ++k) {
            int f = 16 * k + fg * 2;
            float y0 = fmaxf(lo32(acc[i][k]) + sBF[f], 0.f);
            float y1 = fmaxf(hi32(acc[i][k]) + sBF[f + 1], 0.f);
            float s = y0 + y1;
            float s2 = y0 * y0 + y1 * y1;
            s  += __shfl_xor_sync(0xffffffffu, s, 1);
            s2 += __shfl_xor_sync(0xffffffffu, s2, 1);
            s  += __shfl_xor_sync(0xffffffffu, s, 2);
            s2 += __shfl_xor_sync(0xffffffffu, s2, 2);
            float mean = s * 0.125f;
            float var = s2 * 0.125f - mean * mean;
            float sc = rsqrtf(var + EPSF);
            float o0 = (y0 - mean) * sc * sGW[f] + sGB[f];
            float o1 = (y1 - mean) * sc * sGW[f + 1] + sGB[f + 1];
            *(float2*)(orow_out + f) = make_float2(o0, o1);
        }
    }
}

// ================= launch =================
extern "C" void kernel_launch(void* const* d_in, const int* in_sizes, int n_in,
                              void* d_out, int out_size) {
    (void)in_sizes; (void)n_in; (void)out_size;
    const float* x    = (const float*)d_in[0];
    const float* Wc   = (const float*)d_in[1];
    const float* bc   = (const float*)d_in[2];
    const float* ginw = (const float*)d_in[3];
    const float* ginb = (const float*)d_in[4];
    const float* Q    = (const float*)d_in[5];
    const float* Wk   = (const float*)d_in[6];
    const float* bk   = (const float*)d_in[7];
    const float* W1   = (const float*)d_in[8];
    const float* b1   = (const float*)d_in[9];
    const float* bnw  = (const float*)d_in[10];
    const float* bnb  = (const float*)d_in[11];
    const float* bnrm = (const float*)d_in[12];
    const float* bnrv = (const float*)d_in[13];
    const float* gow  = (const float*)d_in[14];
    const float* gob  = (const float*)d_in[15];
    float* out = (float*)d_out;

    cudaFuncSetAttribute(k_attention, cudaFuncAttributeMaxDynamicSharedMemorySize, SMEM_ATT_BYTES);
    cudaFuncSetAttribute(k_mlp, cudaFuncAttributeMaxDynamicSharedMemorySize, SMEM_MLP_BYTES);

    k_precompP<<<208, 256>>>(Q, Wk, bk);                       // launch 1
    k_foldW1<<<128, 256>>>(W1, b1, bnw, bnb, bnrm, bnrv);      // launch 2
    k_nop<<<1, 32>>>();                                        // launch 3
    k_attention<<<1024, 256, SMEM_ATT_BYTES>>>(x, Wc, bc, ginw, ginb);  // launch 4 (ncu target)
    k_mlp<<<104, 256, SMEM_MLP_BYTES>>>(gow, gob, out);        // launch 5
}

// round 11
// speedup vs baseline: 1.0280x; 1.0217x over previous
#include <cuda_runtime.h>
#include <cuda_bf16.h>
#include <cstdint>

typedef unsigned long long ull;

#define EPSF 1e-5f

// ---------------- scratch ----------------
__device__ __nv_bfloat16 g_P2h[(size_t)13 * 256 * 256];  // [e][col][k] hi plane
__device__ __nv_bfloat16 g_P2l[(size_t)13 * 256 * 256];  // [e][col][k] lo plane
__device__ float g_Pb[208 * 16];                // [m][a16], 0.5 folded bias
__device__ float g_W1T[256 * 128];              // [c][f], BN-scale folded
__device__ float g_bf[128];                     // folded bias
__device__ float g_att[(size_t)13312 * 256];    // attention out, row = a*1024 + b

// ---------------- helpers ----------------
__device__ __forceinline__ ull fma2(ull a, ull b, ull c) {
    ull d;
    asm("fma.rn.f32x2 %0, %1, %2, %3;" : "=l"(d) : "l"(a), "l"(b), "l"(c));
    return d;
}
__device__ __forceinline__ ull dup2(float v) {
    ull d; unsigned r = __float_as_uint(v);
    asm("mov.b64 %0, {%1, %1};" : "=l"(d) : "r"(r));
    return d;
}
__device__ __forceinline__ float lo32(ull a) { return __uint_as_float((unsigned)(a & 0xffffffffull)); }
__device__ __forceinline__ float hi32(ull a) { return __uint_as_float((unsigned)(a >> 32)); }

__device__ __forceinline__ void cpa16(unsigned dst, const void* src) {
    asm volatile("cp.async.ca.shared.global [%0], [%1], 16;" :: "r"(dst), "l"(src));
}
__device__ __forceinline__ void cpa_commit() {
    asm volatile("cp.async.commit_group;" ::: "memory");
}
__device__ __forceinline__ void cpa_wait0() {
    asm volatile("cp.async.wait_group 0;" ::: "memory");
}
__device__ __forceinline__ unsigned s32(const void* p) {
    return (unsigned)__cvta_generic_to_shared(p);
}
__device__ __forceinline__ void ldmx4(unsigned* r, unsigned addr) {
    asm volatile("ldmatrix.sync.aligned.m8n8.x4.shared.b16 {%0,%1,%2,%3}, [%4];"
        : "=r"(r[0]), "=r"(r[1]), "=r"(r[2]), "=r"(r[3]) : "r"(addr));
}
__device__ __forceinline__ void ldmx2(unsigned* r, unsigned addr) {
    asm volatile("ldmatrix.sync.aligned.m8n8.x2.shared.b16 {%0,%1}, [%2];"
        : "=r"(r[0]), "=r"(r[1]) : "r"(addr));
}
__device__ __forceinline__ void mma16816(float* d, const unsigned* a, const unsigned* b) {
    asm volatile(
        "mma.sync.aligned.m16n8k16.row.col.f32.bf16.bf16.f32 "
        "{%0,%1,%2,%3}, {%4,%5,%6,%7}, {%8,%9}, {%0,%1,%2,%3};"
        : "+f"(d[0]), "+f"(d[1]), "+f"(d[2]), "+f"(d[3])
        : "r"(a[0]), "r"(a[1]), "r"(a[2]), "r"(a[3]), "r"(b[0]), "r"(b[1]));
}

// ================= dummy (ncu capture alignment: capture = 4th launch) =====
__global__ void k_nop() {}

// ================= fold Q into Wk, bf16-split, [e][col][k] layout ==========
__global__ void k_precompP2(const float* __restrict__ Q,
                            const float* __restrict__ Wk,
                            const float* __restrict__ bk) {
    int e = blockIdx.x >> 4;       // 0..12
    int S = blockIdx.x & 15;       // 0..15 (= hk)
    int k = threadIdx.x;           // 0..255
    int m = S * 13 + e;            // 0..207
    const float* qp = Q + m * 4;
    float q0 = qp[0], q1 = qp[1], q2 = qp[2], q3 = qp[3];
    __nv_bfloat16* dh = g_P2h + ((size_t)e * 256 + S * 16) * 256 + k;
    __nv_bfloat16* dl = g_P2l + ((size_t)e * 256 + S * 16) * 256 + k;
    #pragma unroll
    for (int a = 0; a < 13; ++a) {
        const float* wv = Wk + (size_t)(a * 64 + S * 4) * 256 + k;
        float s = 0.5f * (q0 * wv[0] + q1 * wv[256] + q2 * wv[512] + q3 * wv[768]);
        __nv_bfloat16 hi = __float2bfloat16(s);
        dh[(size_t)a * 256] = hi;
        dl[(size_t)a * 256] = __float2bfloat16(s - __bfloat162float(hi));
    }
    #pragma unroll
    for (int a = 13; a < 16; ++a) {
        dh[(size_t)a * 256] = __float2bfloat16(0.f);
        dl[(size_t)a * 256] = __float2bfloat16(0.f);
    }
    if (k < 16) {
        float v = 0.f;
        if (k < 13) {
            const float* bb = bk + k * 64 + S * 4;
            v = 0.5f * (q0 * bb[0] + q1 * bb[1] + q2 * bb[2] + q3 * bb[3]);
        }
        g_Pb[m * 16 + k] = v;
    }
}

// ================= fold BN into W1, transpose =================
__global__ void k_foldW1(const float* __restrict__ W1, const float* __restrict__ b1,
                         const float* __restrict__ bnw, const float* __restrict__ bnb,
                         const float* __restrict__ bnrm, const float* __restrict__ bnrv) {
    int f = blockIdx.x;    // 0..127
    int c = threadIdx.x;   // 0..255
    float s = bnw[f] * rsqrtf(bnrv[f] + EPSF);
    g_W1T[c * 128 + f] = W1[f * 256 + c] * s;
    if (c == 0) g_bf[f] = b1[f] * s + bnb[f] - bnrm[f] * s;
}

// ================= attention: conv+GN, bf16-split MMA logits, softmax, AV ==
// smem byte layout:
//   AH  @ 0       : 64 rows x 528 B (A hi plane, bf16, row = t, k contiguous)
//   AL  @ 33792   : same (lo plane)
//   BS  @ 67584   : 2 bufs x 2 planes x 128 q x 48 B  (24,576 B)
//   VT  @ 92160   : 256 c x 68 t fp32 (69,632 B)    -- AV operand
//   MS  @ 161792  : 64 t x 132 col fp32 (33,792 B)  -- logits; sx aliased here
//   PB  @ 195584  : 16 warps x 64 fp32 (4,096 B)
#define AH_OFF  0
#define AL_OFF  33792
#define BS_OFF  67584
#define VT_OFF  92160
#define MS_OFF  161792
#define PBF_OFF 195584
#define SMEM_ATT_BYTES 199680

__global__ void __launch_bounds__(512, 1) k_attention(
    const float* __restrict__ x, const float* __restrict__ Wc,
    const float* __restrict__ bc, const float* __restrict__ ginw,
    const float* __restrict__ ginb) {
    extern __shared__ char smc[];
    __nv_bfloat16* AH = (__nv_bfloat16*)(smc + AH_OFF);
    __nv_bfloat16* AL = (__nv_bfloat16*)(smc + AL_OFF);
    char* BS   = smc + BS_OFF;
    float* VT  = (float*)(smc + VT_OFF);
    float* MS  = (float*)(smc + MS_OFF);
    float* sx  = MS;                      // alias: x staging, pre-GEMM only
    float* pbuf = (float*)(smc + PBF_OFF);
    const int tid = threadIdx.x;
    const int b = blockIdx.x;

    // stage x[b] (600 floats)
    for (int i = tid; i < 150; i += 512)
        ((float4*)sx)[i] = ((const float4*)(x + (size_t)b * 600))[i];
    __syncthreads();

    // ---- conv1x1 + GroupNorm(16 groups): thread pair per channel ----
    {
        const int c = tid >> 1;
        const int th = tid & 1;
        float wr[10];
        #pragma unroll
        for (int i = 0; i < 10; ++i) wr[i] = Wc[c * 10 + i];
        const float bb = bc[c];
        float vv[30];
        float s1 = 0.f, s2 = 0.f;
        #pragma unroll 6
        for (int tt = 0; tt < 30; ++tt) {
            const float* xr = sx + (th * 30 + tt) * 10;
            float h = bb;
            #pragma unroll
            for (int i = 0; i < 10; ++i) h = fmaf(wr[i], xr[i], h);
            vv[tt] = h; s1 += h; s2 = fmaf(h, h, s2);
        }
        #pragma unroll
        for (int o = 16; o; o >>= 1) {
            s1 += __shfl_xor_sync(0xffffffffu, s1, o);
            s2 += __shfl_xor_sync(0xffffffffu, s2, o);
        }
        float mean = s1 * (1.f / 960.f);
        float var = s2 * (1.f / 960.f) - mean * mean;
        float sc = ginw[c] * rsqrtf(var + EPSF);
        float sh = ginb[c] - mean * sc;
        __syncthreads();   // all conv reads of sx done before anything later hits MS
        #pragma unroll 6
        for (int tt = 0; tt < 30; ++tt) {
            int t = th * 30 + tt;
            float v = fmaf(vv[tt], sc, sh);
            VT[c * 68 + t] = v;
            __nv_bfloat16 hi = __float2bfloat16(v);
            AH[t * 264 + c] = hi;
            AL[t * 264 + c] = __float2bfloat16(v - __bfloat162float(hi));
        }
        if (th == 1) {
            VT[c * 68 + 60] = 0.f; VT[c * 68 + 61] = 0.f;
            VT[c * 68 + 62] = 0.f; VT[c * 68 + 63] = 0.f;
        }
    }
    // zero A pad rows t = 60..63 (both planes, incl. col pad)
    for (int i = tid; i < 4 * 264; i += 512) {
        int rr = 60 + i / 264, cc = i % 264;
        AH[rr * 264 + cc] = __float2bfloat16(0.f);
        AL[rr * 264 + cc] = __float2bfloat16(0.f);
    }
    __syncthreads();

    const int e0 = (b * 13) >> 10;
    const int e12 = (b * 13 + 12) >> 10;
    const int nchunks = (e0 == e12) ? 2 : 4;
    const int w = tid >> 5;
    const int lane = tid & 31;
    const int mt = w >> 2;          // m-tile 0..3 (rows mt*16..+16)
    const int nq = w & 3;           // n-quad  0..3 (n-tiles nq*4..+4)
    const int g = lane >> 2;
    const int t4 = lane & 3;

    // B staging coords: one 16B per thread per k-step
    const int spl = tid >> 8;              // 0 = hi, 1 = lo
    const int sq = tid & 127;              // local col 0..127
    const int sh16 = (tid >> 7) & 1;       // 16B half of 32B k-row
    const unsigned bs_base = s32(BS) + (unsigned)(spl * 6144 + sq * 48 + sh16 * 16);
    const __nv_bfloat16* gsrc = spl ? g_P2l : g_P2h;

    // A ldmatrix base addresses (per warp)
    const unsigned aAH = s32(AH) + (unsigned)((mt * 16 + (lane & 15)) * 528 + ((lane >> 4) & 1) * 16);
    const unsigned aAL = s32(AL) + (unsigned)((mt * 16 + (lane & 15)) * 528 + ((lane >> 4) & 1) * 16);
    const unsigned bsm = s32(BS);

    for (int chunk = 0; chunk < nchunks; ++chunk) {
        const int ec = e0 + (chunk >> 1);
        const size_t qbase = ((size_t)ec * 256 + (chunk & 1) * 128 + sq) * 256 + sh16 * 8;

        float D[16];
        #pragma unroll
        for (int i = 0; i < 16; ++i) D[i] = 0.f;

        // prologue: prefetch k-step 0
        cpa16(bs_base, gsrc + qbase);
        cpa_commit();

        for (int ks = 0; ks < 16; ++ks) {
            cpa_wait0();
            __syncthreads();
            if (ks + 1 < 16) {
                cpa16(bs_base + ((ks + 1) & 1) * 12288u, gsrc + qbase + (size_t)(ks + 1) * 16);
                cpa_commit();
            }
            const unsigned bufof = (unsigned)((ks & 1) * 12288);
            unsigned ah[4], al[4];
            ldmx4(ah, aAH + ks * 32);
            ldmx4(al, aAL + ks * 32);
            #pragma unroll
            for (int i = 0; i < 4; ++i) {
                int nt = nq * 4 + i;
                unsigned baddr = bsm + bufof + (unsigned)((nt * 8 + (lane & 7)) * 48 + ((lane >> 3) & 1) * 16);
                unsigned bh[2], bl[2];
                ldmx2(bh, baddr);
                ldmx2(bl, baddr + 6144u);
                mma16816(D + i * 4, ah, bh);
                mma16816(D + i * 4, ah, bl);
                mma16816(D + i * 4, al, bh);
            }
        }

        // D -> MS (rows = t, cols = chunk-local 0..127, stride 132)
        #pragma unroll
        for (int i = 0; i < 4; ++i) {
            int nt = nq * 4 + i;
            int row = mt * 16 + g;
            *(float2*)&MS[row * 132 + nt * 8 + t4 * 2] = make_float2(D[i * 4 + 0], D[i * 4 + 1]);
            *(float2*)&MS[(row + 8) * 132 + nt * 8 + t4 * 2] = make_float2(D[i * 4 + 2], D[i * 4 + 3]);
        }
        __syncthreads();

        // ---- epilogue: 104 rows (8 hk x 13 j) spread over 16 warps ----
        for (int r = w; r < 104; r += 16) {
            int hkl = r / 13;
            int j = r - hkl * 13;
            int e = (b * 13 + j) >> 10;
            if (e != ec) continue;
            int hk = ((chunk & 1) << 3) + hkl;
            int m = hk * 13 + e;
            int colb = hkl * 16;
            int val = j * 240 + lane * 4;
            int t = val / 52;
            int a = (val - t * 52) >> 2;
            float l1 = MS[t * 132 + colb + a] + g_Pb[m * 16 + a];
            float l2 = -1e30f;
            if (lane < 28) {
                int val2 = val + 128;
                int t2 = val2 / 52;
                int a2 = (val2 - t2 * 52) >> 2;
                l2 = MS[t2 * 132 + colb + a2] + g_Pb[m * 16 + a2];
            }
            float mx = fmaxf(l1, l2);
            #pragma unroll
            for (int o = 16; o; o >>= 1) mx = fmaxf(mx, __shfl_xor_sync(0xffffffffu, mx, o));
            float x1 = __expf(l1 - mx);
            float x2 = (lane < 28) ? __expf(l2 - mx) : 0.f;
            float sum = x1 + x2;
            #pragma unroll
            for (int o = 16; o; o >>= 1) sum += __shfl_xor_sync(0xffffffffu, sum, o);
            float inv = 1.f / sum;
            pbuf[w * 64 + lane] = x1 * inv;
            if (lane < 28) pbuf[w * 64 + 32 + lane] = x2 * inv;
            __syncwarp();
            // AV: lanes 0..15 sum t 0..29, lanes 16..31 sum t 30..59
            int dh = lane & 15;
            int toff = (lane >> 4) * 30;
            const float* vcol = VT + (hk * 16 + dh) * 68 + toff;
            const float* pb = pbuf + w * 64 + toff;
            float a0 = 0.f, a1 = 0.f;
            #pragma unroll
            for (int tt = 0; tt < 15; ++tt) {
                a0 = fmaf(pb[tt], vcol[tt], a0);
                a1 = fmaf(pb[tt + 15], vcol[tt + 15], a1);
            }
            float acv = a0 + a1;
            acv += __shfl_xor_sync(0xffffffffu, acv, 16);
            if (lane < 16) {
                int bq = (b * 13 + j) & 1023;
                g_att[(size_t)((m >> 4) * 1024 + bq) * 256 + ((m & 15) << 4) + dh] = acv;
            }
            __syncwarp();
        }
        __syncthreads();   // MS reads done before next chunk overwrites
    }
}

// ================= MLP + BN + ReLU + GroupNorm + permute =================
// 104 blocks x 128 rows (round-3 proven version, 37.4 us)
#define SO_OFF   0                          // [128][260]
#define SWC_OFF  (128*260)                  // [64][132]
#define SBF_OFF  (SWC_OFF + 64*132)
#define SGW_OFF  (SBF_OFF + 128)
#define SGB_OFF  (SGW_OFF + 128)
#define SMEM_MLP_FLOATS (SGB_OFF + 128)
#define SMEM_MLP_BYTES  (SMEM_MLP_FLOATS * 4)

__global__ void __launch_bounds__(256, 1) k_mlp(const float* __restrict__ gow,
                                                const float* __restrict__ gob,
                                                float* __restrict__ out) {
    extern __shared__ float sm[];
    float* sO  = sm + SO_OFF;
    float* sW  = sm + SWC_OFF;
    float* sBF = sm + SBF_OFF;
    float* sGW = sm + SGW_OFF;
    float* sGB = sm + SGB_OFF;
    const int tid = threadIdx.x;
    const int row0 = blockIdx.x * 128;

    for (int q = tid; q < 8192; q += 256) {
        int row = q >> 6, c4 = q & 63;
        *(float4*)(sO + row * 260 + c4 * 4) =
            *(const float4*)(g_att + (size_t)(row0 + row) * 256 + c4 * 4);
    }
    if (tid < 128) { sBF[tid] = g_bf[tid]; sGW[tid] = gow[tid]; sGB[tid] = gob[tid]; }

    const int rq = tid >> 3;       // 0..31
    const int fg = tid & 7;        // f = 16k + fg*2 + {0,1}
    ull acc[4][8];
    #pragma unroll
    for (int i = 0; i < 4; ++i)
        #pragma unroll
        for (int k = 0; k < 8; ++k) acc[i][k] = 0ull;

    for (int cc = 0; cc < 4; ++cc) {
        __syncthreads();
        for (int q = tid; q < 2048; q += 256) {
            int c = q >> 5, f4 = q & 31;
            *(float4*)(sW + c * 132 + f4 * 4) =
                *(const float4*)(g_W1T + (size_t)(cc * 64 + c) * 128 + f4 * 4);
        }
        __syncthreads();
        #pragma unroll 4
        for (int c = 0; c < 64; ++c) {
            const float* wr = sW + c * 132 + fg * 2;
            ull wv[8];
            #pragma unroll
            for (int k = 0; k < 8; ++k) wv[k] = *(const ull*)(wr + 16 * k);
            int cg = cc * 64 + c;
            #pragma unroll
            for (int i = 0; i < 4; ++i) {
                ull od = dup2(sO[(rq + 32 * i) * 260 + cg]);
                #pragma unroll
                for (int k = 0; k < 8; ++k)
                    acc[i][k] = fma2(od, wv[k], acc[i][k]);
            }
        }
    }

    #pragma unroll
    for (int i = 0; i < 4; ++i) {
        int r = row0 + rq + 32 * i;
        float* orow_out = out + (size_t)((r & 1023) * 13 + (r >> 10)) * 128;
        #pragma unroll
        for (int k = 0; k < 8; ++k) {
            int f = 16 * k + fg * 2;
            float y0 = fmaxf(lo32(acc[i][k]) + sBF[f], 0.f);
            float y1 = fmaxf(hi32(acc[i][k]) + sBF[f + 1], 0.f);
            float s = y0 + y1;
            float s2 = y0 * y0 + y1 * y1;
            s  += __shfl_xor_sync(0xffffffffu, s, 1);
            s2 += __shfl_xor_sync(0xffffffffu, s2, 1);
            s  += __shfl_xor_sync(0xffffffffu, s, 2);
            s2 += __shfl_xor_sync(0xffffffffu, s2, 2);
            float mean = s * 0.125f;
            float var = s2 * 0.125f - mean * mean;
            float sc = rsqrtf(var + EPSF);
            float o0 = (y0 - mean) * sc * sGW[f] + sGB[f];
            float o1 = (y1 - mean) * sc * sGW[f + 1] + sGB[f + 1];
            *(float2*)(orow_out + f) = make_float2(o0, o1);
        }
    }
}

// ================= launch =================
extern "C" void kernel_launch(void* const* d_in, const int* in_sizes, int n_in,
                              void* d_out, int out_size) {
    (void)in_sizes; (void)n_in; (void)out_size;
    const float* x    = (const float*)d_in[0];
    const float* Wc   = (const float*)d_in[1];
    const float* bc   = (const float*)d_in[2];
    const float* ginw = (const float*)d_in[3];
    const float* ginb = (const float*)d_in[4];
    const float* Q    = (const float*)d_in[5];
    const float* Wk   = (const float*)d_in[6];
    const float* bk   = (const float*)d_in[7];
    const float* W1   = (const float*)d_in[8];
    const float* b1   = (const float*)d_in[9];
    const float* bnw  = (const float*)d_in[10];
    const float* bnb  = (const float*)d_in[11];
    const float* bnrm = (const float*)d_in[12];
    const float* bnrv = (const float*)d_in[13];
    const float* gow  = (const float*)d_in[14];
    const float* gob  = (const float*)d_in[15];
    float* out = (float*)d_out;

    cudaFuncSetAttribute(k_attention, cudaFuncAttributeMaxDynamicSharedMemorySize, SMEM_ATT_BYTES);
    cudaFuncSetAttribute(k_mlp, cudaFuncAttributeMaxDynamicSharedMemorySize, SMEM_MLP_BYTES);

    k_precompP2<<<208, 256>>>(Q, Wk, bk);                      // launch 1
    k_foldW1<<<128, 256>>>(W1, b1, bnw, bnb, bnrm, bnrv);      // launch 2
    k_nop<<<1, 32>>>();                                        // launch 3
    k_attention<<<1024, 512, SMEM_ATT_BYTES>>>(x, Wc, bc, ginw, ginb);  // launch 4 (ncu target)
    k_mlp<<<104, 256, SMEM_MLP_BYTES>>>(gow, gob, out);        // launch 5
}

// round 12
// speedup vs baseline: 1.2273x; 1.1939x over previous
#include <cuda_runtime.h>
#include <cuda_bf16.h>
#include <cstdint>

typedef unsigned long long ull;

#define EPSF 1e-5f

// ---------------- scratch ----------------
__device__ __nv_bfloat16 g_P2h[(size_t)13 * 256 * 256];  // [e][col][k] hi plane
__device__ __nv_bfloat16 g_P2l[(size_t)13 * 256 * 256];  // [e][col][k] lo plane
__device__ float g_Pb[208 * 16];                // [m][a16], 0.5 folded bias
__device__ float g_W1T[256 * 128];              // [c][f], BN-scale folded
__device__ float g_bf[128];                     // folded bias
__device__ float g_att[(size_t)13312 * 256];    // attention out, row = a*1024 + b

// ---------------- helpers ----------------
__device__ __forceinline__ ull fma2(ull a, ull b, ull c) {
    ull d;
    asm("fma.rn.f32x2 %0, %1, %2, %3;" : "=l"(d) : "l"(a), "l"(b), "l"(c));
    return d;
}
__device__ __forceinline__ ull dup2(float v) {
    ull d; unsigned r = __float_as_uint(v);
    asm("mov.b64 %0, {%1, %1};" : "=l"(d) : "r"(r));
    return d;
}
__device__ __forceinline__ float lo32(ull a) { return __uint_as_float((unsigned)(a & 0xffffffffull)); }
__device__ __forceinline__ float hi32(ull a) { return __uint_as_float((unsigned)(a >> 32)); }

__device__ __forceinline__ void cpa16(unsigned dst, const void* src) {
    asm volatile("cp.async.ca.shared.global [%0], [%1], 16;" :: "r"(dst), "l"(src));
}
__device__ __forceinline__ void cpa_commit() {
    asm volatile("cp.async.commit_group;" ::: "memory");
}
__device__ __forceinline__ void cpa_wait0() {
    asm volatile("cp.async.wait_group 0;" ::: "memory");
}
__device__ __forceinline__ unsigned s32(const void* p) {
    return (unsigned)__cvta_generic_to_shared(p);
}
__device__ __forceinline__ void ldmx4(unsigned* r, unsigned addr) {
    asm volatile("ldmatrix.sync.aligned.m8n8.x4.shared.b16 {%0,%1,%2,%3}, [%4];"
        : "=r"(r[0]), "=r"(r[1]), "=r"(r[2]), "=r"(r[3]) : "r"(addr));
}
__device__ __forceinline__ void mma16816(float* d, const unsigned* a, const unsigned* b) {
    asm volatile(
        "mma.sync.aligned.m16n8k16.row.col.f32.bf16.bf16.f32 "
        "{%0,%1,%2,%3}, {%4,%5,%6,%7}, {%8,%9}, {%0,%1,%2,%3};"
        : "+f"(d[0]), "+f"(d[1]), "+f"(d[2]), "+f"(d[3])
        : "r"(a[0]), "r"(a[1]), "r"(a[2]), "r"(a[3]), "r"(b[0]), "r"(b[1]));
}

// ================= dummy (ncu capture alignment: capture = 4th launch) =====
__global__ void k_nop() {}

// ================= fold Q into Wk, bf16-split, [e][col][k] layout ==========
__global__ void k_precompP2(const float* __restrict__ Q,
                            const float* __restrict__ Wk,
                            const float* __restrict__ bk) {
    int e = blockIdx.x >> 4;       // 0..12
    int S = blockIdx.x & 15;       // 0..15 (= hk)
    int k = threadIdx.x;           // 0..255
    int m = S * 13 + e;            // 0..207
    const float* qp = Q + m * 4;
    float q0 = qp[0], q1 = qp[1], q2 = qp[2], q3 = qp[3];
    __nv_bfloat16* dh = g_P2h + ((size_t)e * 256 + S * 16) * 256 + k;
    __nv_bfloat16* dl = g_P2l + ((size_t)e * 256 + S * 16) * 256 + k;
    #pragma unroll
    for (int a = 0; a < 13; ++a) {
        const float* wv = Wk + (size_t)(a * 64 + S * 4) * 256 + k;
        float s = 0.5f * (q0 * wv[0] + q1 * wv[256] + q2 * wv[512] + q3 * wv[768]);
        __nv_bfloat16 hi = __float2bfloat16(s);
        dh[(size_t)a * 256] = hi;
        dl[(size_t)a * 256] = __float2bfloat16(s - __bfloat162float(hi));
    }
    #pragma unroll
    for (int a = 13; a < 16; ++a) {
        dh[(size_t)a * 256] = __float2bfloat16(0.f);
        dl[(size_t)a * 256] = __float2bfloat16(0.f);
    }
    if (k < 16) {
        float v = 0.f;
        if (k < 13) {
            const float* bb = bk + k * 64 + S * 4;
            v = 0.5f * (q0 * bb[0] + q1 * bb[1] + q2 * bb[2] + q3 * bb[3]);
        }
        g_Pb[m * 16 + k] = v;
    }
}

// ================= fold BN into W1, transpose =================
__global__ void k_foldW1(const float* __restrict__ W1, const float* __restrict__ b1,
                         const float* __restrict__ bnw, const float* __restrict__ bnb,
                         const float* __restrict__ bnrm, const float* __restrict__ bnrv) {
    int f = blockIdx.x;    // 0..127
    int c = threadIdx.x;   // 0..255
    float s = bnw[f] * rsqrtf(bnrv[f] + EPSF);
    g_W1T[c * 128 + f] = W1[f * 256 + c] * s;
    if (c == 0) g_bf[f] = b1[f] * s + bnb[f] - bnrm[f] * s;
}

// ================= attention: conv+GN, bf16-split MMA logits, softmax, AV ==
// smem byte layout:
//   AH @ 0       : 64 rows x 528 B (A hi plane, bf16, row = t)
//   AL @ 33792   : same (lo plane)
//   BS @ 67584   : 2 bufs x [2 planes x 128 col x 80 B] (40,960 B; 64B payload = 2 k-steps)
//   VT @ 108544  : 256 c x 68 t fp32 (69,632 B)
//   MS @ 178176  : 64 t x 132 col fp32 (33,792 B); sx aliased here
//   PB @ 211968  : 16 warps x 64 fp32 (4,096 B)
#define AH_OFF  0
#define AL_OFF  33792
#define BS_OFF  67584
#define VT_OFF  108544
#define MS_OFF  178176
#define PBF_OFF 211968
#define SMEM_ATT_BYTES 216064
#define BS_BUF 20480

__global__ void __launch_bounds__(512, 1) k_attention(
    const float* __restrict__ x, const float* __restrict__ Wc,
    const float* __restrict__ bc, const float* __restrict__ ginw,
    const float* __restrict__ ginb) {
    extern __shared__ char smc[];
    __nv_bfloat16* AH = (__nv_bfloat16*)(smc + AH_OFF);
    __nv_bfloat16* AL = (__nv_bfloat16*)(smc + AL_OFF);
    float* VT  = (float*)(smc + VT_OFF);
    float* MS  = (float*)(smc + MS_OFF);
    float* sx  = MS;                      // alias: x staging, pre-GEMM only
    float* pbuf = (float*)(smc + PBF_OFF);
    const int tid = threadIdx.x;
    const int b = blockIdx.x;

    // stage x[b] (600 floats)
    for (int i = tid; i < 150; i += 512)
        ((float4*)sx)[i] = ((const float4*)(x + (size_t)b * 600))[i];
    __syncthreads();

    // ---- conv1x1 + GroupNorm(16 groups): thread pair per channel ----
    {
        const int c = tid >> 1;
        const int th = tid & 1;
        float wr[10];
        #pragma unroll
        for (int i = 0; i < 10; ++i) wr[i] = Wc[c * 10 + i];
        const float bb = bc[c];
        float vv[30];
        float s1 = 0.f, s2 = 0.f;
        #pragma unroll 6
        for (int tt = 0; tt < 30; ++tt) {
            const float* xr = sx + (th * 30 + tt) * 10;
            float h = bb;
            #pragma unroll
            for (int i = 0; i < 10; ++i) h = fmaf(wr[i], xr[i], h);
            vv[tt] = h; s1 += h; s2 = fmaf(h, h, s2);
        }
        #pragma unroll
        for (int o = 16; o; o >>= 1) {
            s1 += __shfl_xor_sync(0xffffffffu, s1, o);
            s2 += __shfl_xor_sync(0xffffffffu, s2, o);
        }
        float mean = s1 * (1.f / 960.f);
        float var = s2 * (1.f / 960.f) - mean * mean;
        float sc = ginw[c] * rsqrtf(var + EPSF);
        float sh = ginb[c] - mean * sc;
        __syncthreads();   // all conv reads of sx done before MS is reused
        #pragma unroll 6
        for (int tt = 0; tt < 30; ++tt) {
            int t = th * 30 + tt;
            float v = fmaf(vv[tt], sc, sh);
            VT[c * 68 + t] = v;
            __nv_bfloat16 hi = __float2bfloat16(v);
            AH[t * 264 + c] = hi;
            AL[t * 264 + c] = __float2bfloat16(v - __bfloat162float(hi));
        }
        if (th == 1) {
            VT[c * 68 + 60] = 0.f; VT[c * 68 + 61] = 0.f;
            VT[c * 68 + 62] = 0.f; VT[c * 68 + 63] = 0.f;
        }
    }
    // zero A pad rows t = 60..63 (both planes, incl. col pad)
    for (int i = tid; i < 4 * 264; i += 512) {
        int rr = 60 + i / 264, cc = i % 264;
        AH[rr * 264 + cc] = __float2bfloat16(0.f);
        AL[rr * 264 + cc] = __float2bfloat16(0.f);
    }
    __syncthreads();

    const int e0 = (b * 13) >> 10;
    const int e12 = (b * 13 + 12) >> 10;
    const int nchunks = (e0 == e12) ? 2 : 4;
    const int w = tid >> 5;
    const int lane = tid & 31;
    const int mt = w >> 2;          // (GEMM warps w<8): m-tile 0..1 (rows mt*32..+32)
    const int nq = w & 3;           // n-quad 0..3 (cols nq*32..+32)
    const int g = lane >> 2;
    const int t4 = lane & 3;

    // B staging coords: two 16B per thread per round (one 32B chunk)
    const int spl = tid >> 8;              // 0 = hi, 1 = lo
    const int sq = (tid & 255) >> 1;       // local col 0..127
    const int sh2 = (tid & 1) * 2;         // 16B slot 0 or 2
    const unsigned bs_t = s32(smc + BS_OFF) + (unsigned)(spl * 10240 + sq * 80 + sh2 * 16);
    const __nv_bfloat16* gsrc = spl ? g_P2l : g_P2h;

    // A ldmatrix lane-address components (per warp, GEMM warps)
    const unsigned aA_lane = (unsigned)((lane & 15) * 528 + ((lane >> 4) & 1) * 16);
    const unsigned aAH0 = s32(AH) + (unsigned)(mt * 32 * 528) + aA_lane;         // rh=0
    const unsigned aAH1 = aAH0 + 16 * 528;                                       // rh=1
    const unsigned aAL0 = s32(AL) + (unsigned)(mt * 32 * 528) + aA_lane;
    const unsigned aAL1 = aAL0 + 16 * 528;
    // B ldmatrix lane address (pair p covers n-tiles 2p,2p+1)
    const int bgrp = lane >> 3, blr = lane & 7;
    const unsigned bs_lane = (unsigned)((nq * 32 + (bgrp >> 1) * 8 + blr) * 80 + (bgrp & 1) * 16);
    const unsigned bsm = s32(smc + BS_OFF);

    for (int chunk = 0; chunk < nchunks; ++chunk) {
        const int ec = e0 + (chunk >> 1);
        const size_t qb = ((size_t)ec * 256 + (chunk & 1) * 128 + sq) * 256 + sh2 * 8;

        float D[2][16];
        #pragma unroll
        for (int i = 0; i < 2; ++i)
            #pragma unroll
            for (int j = 0; j < 16; ++j) D[i][j] = 0.f;

        // prologue: prefetch round 0
        {
            const __nv_bfloat16* s = gsrc + qb;
            cpa16(bs_t, s);
            cpa16(bs_t + 16, s + 8);
            cpa_commit();
        }

        for (int r = 0; r < 8; ++r) {
            cpa_wait0();
            __syncthreads();
            if (r + 1 < 8) {
                unsigned d = bs_t + (unsigned)(((r + 1) & 1) * BS_BUF);
                const __nv_bfloat16* s = gsrc + qb + (size_t)(r + 1) * 32;
                cpa16(d, s);
                cpa16(d + 16, s + 8);
                cpa_commit();
            }
            if (w < 8) {
                const unsigned bufof = (unsigned)((r & 1) * BS_BUF);
                const unsigned kbyte = (unsigned)(r * 64);
                #pragma unroll
                for (int ks2 = 0; ks2 < 2; ++ks2) {
                    unsigned ah0[4], ah1[4], al0[4], al1[4];
                    ldmx4(ah0, aAH0 + kbyte + ks2 * 32);
                    ldmx4(ah1, aAH1 + kbyte + ks2 * 32);
                    ldmx4(al0, aAL0 + kbyte + ks2 * 32);
                    ldmx4(al1, aAL1 + kbyte + ks2 * 32);
                    unsigned bh0[4], bh1[4], bl0[4], bl1[4];
                    unsigned bb = bsm + bufof + bs_lane + (unsigned)(ks2 * 32);
                    ldmx4(bh0, bb);                       // pair 0 (n-tiles 0,1), hi
                    ldmx4(bh1, bb + 16 * 80);             // pair 1 (n-tiles 2,3), hi
                    ldmx4(bl0, bb + 10240);               // lo plane
                    ldmx4(bl1, bb + 10240 + 16 * 80);
                    #pragma unroll
                    for (int nt = 0; nt < 4; ++nt) {
                        const unsigned* bh = (nt < 2 ? bh0 : bh1) + (nt & 1) * 2;
                        const unsigned* bl = (nt < 2 ? bl0 : bl1) + (nt & 1) * 2;
                        mma16816(D[0] + nt * 4, ah0, bh);
                        mma16816(D[0] + nt * 4, ah0, bl);
                        mma16816(D[0] + nt * 4, al0, bh);
                        mma16816(D[1] + nt * 4, ah1, bh);
                        mma16816(D[1] + nt * 4, ah1, bl);
                        mma16816(D[1] + nt * 4, al1, bh);
                    }
                }
            }
        }

        // D -> MS (rows = t, cols = chunk-local 0..127, stride 132)
        if (w < 8) {
            #pragma unroll
            for (int rh = 0; rh < 2; ++rh) {
                int row = mt * 32 + rh * 16 + g;
                #pragma unroll
                for (int nt = 0; nt < 4; ++nt) {
                    int col = nq * 32 + nt * 8 + t4 * 2;
                    *(float2*)&MS[row * 132 + col] =
                        make_float2(D[rh][nt * 4 + 0], D[rh][nt * 4 + 1]);
                    *(float2*)&MS[(row + 8) * 132 + col] =
                        make_float2(D[rh][nt * 4 + 2], D[rh][nt * 4 + 3]);
                }
            }
        }
        __syncthreads();

        // ---- epilogue: 104 rows (8 hk x 13 j) spread over 16 warps ----
        for (int r = w; r < 104; r += 16) {
            int hkl = r / 13;
            int j = r - hkl * 13;
            int e = (b * 13 + j) >> 10;
            if (e != ec) continue;
            int hk = ((chunk & 1) << 3) + hkl;
            int m = hk * 13 + e;
            int colb = hkl * 16;
            int val = j * 240 + lane * 4;
            int t = val / 52;
            int a = (val - t * 52) >> 2;
            float l1 = MS[t * 132 + colb + a] + g_Pb[m * 16 + a];
            float l2 = -1e30f;
            if (lane < 28) {
                int val2 = val + 128;
                int t2 = val2 / 52;
                int a2 = (val2 - t2 * 52) >> 2;
                l2 = MS[t2 * 132 + colb + a2] + g_Pb[m * 16 + a2];
            }
            float mx = fmaxf(l1, l2);
            #pragma unroll
            for (int o = 16; o; o >>= 1) mx = fmaxf(mx, __shfl_xor_sync(0xffffffffu, mx, o));
            float x1 = __expf(l1 - mx);
            float x2 = (lane < 28) ? __expf(l2 - mx) : 0.f;
            float sum = x1 + x2;
            #pragma unroll
            for (int o = 16; o; o >>= 1) sum += __shfl_xor_sync(0xffffffffu, sum, o);
            float inv = 1.f / sum;
            pbuf[w * 64 + lane] = x1 * inv;
            if (lane < 28) pbuf[w * 64 + 32 + lane] = x2 * inv;
            __syncwarp();
            // AV: lanes 0..15 sum t 0..29, lanes 16..31 sum t 30..59
            int dh = lane & 15;
            int toff = (lane >> 4) * 30;
            const float* vcol = VT + (hk * 16 + dh) * 68 + toff;
            const float* pb = pbuf + w * 64 + toff;
            float a0 = 0.f, a1 = 0.f;
            #pragma unroll
            for (int tt = 0; tt < 15; ++tt) {
                a0 = fmaf(pb[tt], vcol[tt], a0);
                a1 = fmaf(pb[tt + 15], vcol[tt + 15], a1);
            }
            float acv = a0 + a1;
            acv += __shfl_xor_sync(0xffffffffu, acv, 16);
            if (lane < 16) {
                int bq = (b * 13 + j) & 1023;
                g_att[(size_t)((m >> 4) * 1024 + bq) * 256 + ((m & 15) << 4) + dh] = acv;
            }
            __syncwarp();
        }
        __syncthreads();   // MS reads done before next chunk overwrites
    }
}

// ================= MLP + BN + ReLU + GroupNorm + permute =================
// 104 blocks x 128 rows (round-3 proven version, 37.4 us)
#define SO_OFF   0                          // [128][260]
#define SWC_OFF  (128*260)                  // [64][132]
#define SBF_OFF  (SWC_OFF + 64*132)
#define SGW_OFF  (SBF_OFF + 128)
#define SGB_OFF  (SGW_OFF + 128)
#define SMEM_MLP_FLOATS (SGB_OFF + 128)
#define SMEM_MLP_BYTES  (SMEM_MLP_FLOATS * 4)

__global__ void __launch_bounds__(256, 1) k_mlp(const float* __restrict__ gow,
                                                const float* __restrict__ gob,
                                                float* __restrict__ out) {
    extern __shared__ float sm[];
    float* sO  = sm + SO_OFF;
    float* sW  = sm + SWC_OFF;
    float* sBF = sm + SBF_OFF;
    float* sGW = sm + SGW_OFF;
    float* sGB = sm + SGB_OFF;
    const int tid = threadIdx.x;
    const int row0 = blockIdx.x * 128;

    for (int q = tid; q < 8192; q += 256) {
        int row = q >> 6, c4 = q & 63;
        *(float4*)(sO + row * 260 + c4 * 4) =
            *(const float4*)(g_att + (size_t)(row0 + row) * 256 + c4 * 4);
    }
    if (tid < 128) { sBF[tid] = g_bf[tid]; sGW[tid] = gow[tid]; sGB[tid] = gob[tid]; }

    const int rq = tid >> 3;       // 0..31
    const int fg = tid & 7;        // f = 16k + fg*2 + {0,1}
    ull acc[4][8];
    #pragma unroll
    for (int i = 0; i < 4; ++i)
        #pragma unroll
        for (int k = 0; k < 8; ++k) acc[i][k] = 0ull;

    for (int cc = 0; cc < 4; ++cc) {
        __syncthreads();
        for (int q = tid; q < 2048; q += 256) {
            int c = q >> 5, f4 = q & 31;
            *(float4*)(sW + c * 132 + f4 * 4) =
                *(const float4*)(g_W1T + (size_t)(cc * 64 + c) * 128 + f4 * 4);
        }
        __syncthreads();
        #pragma unroll 4
        for (int c = 0; c < 64; ++c) {
            const float* wr = sW + c * 132 + fg * 2;
            ull wv[8];
            #pragma unroll
            for (int k = 0; k < 8; ++k) wv[k] = *(const ull*)(wr + 16 * k);
            int cg = cc * 64 + c;
            #pragma unroll
            for (int i = 0; i < 4; ++i) {
                ull od = dup2(sO[(rq + 32 * i) * 260 + cg]);
                #pragma unroll
                for (int k = 0; k < 8; ++k)
                    acc[i][k] = fma2(od, wv[k], acc[i][k]);
            }
        }
    }

    #pragma unroll
    for (int i = 0; i < 4; ++i) {
        int r = row0 + rq + 32 * i;
        float* orow_out = out + (size_t)((r & 1023) * 13 + (r >> 10)) * 128;
        #pragma unroll
        for (int k = 0; k < 8; ++k) {
            int f = 16 * k + fg * 2;
            float y0 = fmaxf(lo32(acc[i][k]) + sBF[f], 0.f);
            float y1 = fmaxf(hi32(acc[i][k]) + sBF[f + 1], 0.f);
            float s = y0 + y1;
            float s2 = y0 * y0 + y1 * y1;
            s  += __shfl_xor_sync(0xffffffffu, s, 1);
            s2 += __shfl_xor_sync(0xffffffffu, s2, 1);
            s  += __shfl_xor_sync(0xffffffffu, s, 2);
            s2 += __shfl_xor_sync(0xffffffffu, s2, 2);
            float mean = s * 0.125f;
            float var = s2 * 0.125f - mean * mean;
            float sc = rsqrtf(var + EPSF);
            float o0 = (y0 - mean) * sc * sGW[f] + sGB[f];
            float o1 = (y1 - mean) * sc * sGW[f + 1] + sGB[f + 1];
            *(float2*)(orow_out + f) = make_float2(o0, o1);
        }
    }
}

// ================= launch =================
extern "C" void kernel_launch(void* const* d_in, const int* in_sizes, int n_in,
                              void* d_out, int out_size) {
    (void)in_sizes; (void)n_in; (void)out_size;
    const float* x    = (const float*)d_in[0];
    const float* Wc   = (const float*)d_in[1];
    const float* bc   = (const float*)d_in[2];
    const float* ginw = (const float*)d_in[3];
    const float* ginb = (const float*)d_in[4];
    const float* Q    = (const float*)d_in[5];
    const float* Wk   = (const float*)d_in[6];
    const float* bk   = (const float*)d_in[7];
    const float* W1   = (const float*)d_in[8];
    const float* b1   = (const float*)d_in[9];
    const float* bnw  = (const float*)d_in[10];
    const float* bnb  = (const float*)d_in[11];
    const float* bnrm = (const float*)d_in[12];
    const float* bnrv = (const float*)d_in[13];
    const float* gow  = (const float*)d_in[14];
    const float* gob  = (const float*)d_in[15];
    float* out = (float*)d_out;

    cudaFuncSetAttribute(k_attention, cudaFuncAttributeMaxDynamicSharedMemorySize, SMEM_ATT_BYTES);
    cudaFuncSetAttribute(k_mlp, cudaFuncAttributeMaxDynamicSharedMemorySize, SMEM_MLP_BYTES);

    k_precompP2<<<208, 256>>>(Q, Wk, bk);                      // launch 1
    k_foldW1<<<128, 256>>>(W1, b1, bnw, bnb, bnrm, bnrv);      // launch 2
    k_nop<<<1, 32>>>();                                        // launch 3
    k_attention<<<1024, 512, SMEM_ATT_BYTES>>>(x, Wc, bc, ginw, ginb);  // launch 4 (ncu target)
    k_mlp<<<104, 256, SMEM_MLP_BYTES>>>(gow, gob, out);        // launch 5
}